// round 1
// baseline (speedup 1.0000x reference)
#include <cuda_runtime.h>

// Problem constants
#define BATCH 2
#define HEADS 16
#define SEQ   2048
#define DIM   64

// Tiling
#define BQ 64          // q rows per block
#define BK 64          // k cols per tile
#define DQK 128        // concatenated qk dim (Q|Qp)
#define DV 64
#define NWARP 8
#define NTHREAD 256
#define KT_STRIDE 68   // padded row stride (floats) for transposed K tile

// Shared memory layout (floats)
//  Qs : BQ * DQK              = 8192
//  KsT: DQK * KT_STRIDE       = 8704
//  Vs : BK * DV               = 4096
//  Ps : NWARP * 8 * BK        = 4096
#define SMEM_FLOATS (BQ*DQK + DQK*KT_STRIDE + BK*DV + NWARP*8*BK)
#define SMEM_BYTES  (SMEM_FLOATS * 4)

__global__ __launch_bounds__(NTHREAD, 2)
void flash_attn_kernel(const float* __restrict__ Qg,
                       const float* __restrict__ Kg,
                       const float* __restrict__ Vg,
                       const float* __restrict__ Qpg,
                       const float* __restrict__ Kpg,
                       float* __restrict__ Og)
{
    extern __shared__ float smem[];
    float* Qs  = smem;                       // [BQ][DQK]
    float* KsT = Qs + BQ * DQK;              // [DQK][KT_STRIDE]
    float* Vs  = KsT + DQK * KT_STRIDE;      // [BK][DV]
    float* Ps  = Vs + BK * DV;               // [NWARP][8][BK]

    const int bh    = blockIdx.y;            // batch*head index
    const int qtile = blockIdx.x;
    const int tid   = threadIdx.x;
    const int w     = tid >> 5;
    const int lane  = tid & 31;

    const long base = (long)bh * SEQ * DIM;  // elements per (b,h) plane
    const float scale = 0.125f;              // 1/sqrt(64)

    // ---- Load Q tile: concat [Q | Qp] -> Qs[64][128] ----
    {
        const float4* q4  = (const float4*)(Qg  + base + (long)qtile * BQ * DIM);
        const float4* qp4 = (const float4*)(Qpg + base + (long)qtile * BQ * DIM);
        // per source: 64 rows x 16 float4
        for (int i = tid; i < BQ * 16; i += NTHREAD) {
            int row = i >> 4;
            int c4  = i & 15;
            ((float4*)Qs)[row * 32 + c4]      = q4 [row * 16 + c4];
            ((float4*)Qs)[row * 32 + 16 + c4] = qp4[row * 16 + c4];
        }
    }

    // ---- Per-warp state: warp w owns q rows [w*8, w*8+8) of the tile ----
    const int qr0 = w * 8;
    float acc0[8], acc1[8];      // O accumulators: cols (lane) and (lane+32)
    float mrow[8], lrow[8];
    #pragma unroll
    for (int r = 0; r < 8; r++) {
        acc0[r] = 0.f; acc1[r] = 0.f;
        mrow[r] = -1e30f; lrow[r] = 0.f;
    }

    float* PsW = Ps + w * 8 * BK;

    for (int kt = 0; kt < SEQ / BK; kt++) {
        __syncthreads();  // previous tile fully consumed

        // ---- Load K tile transposed: KsT[d][krow], d in [0,128) ----
        {
            const float4* k4  = (const float4*)(Kg  + base + (long)kt * BK * DIM);
            const float4* kp4 = (const float4*)(Kpg + base + (long)kt * BK * DIM);
            for (int i = tid; i < BK * 16; i += NTHREAD) {
                int row = i >> 4;
                int c4  = i & 15;
                int d   = c4 * 4;
                float4 a = k4[row * 16 + c4];
                KsT[(d + 0) * KT_STRIDE + row] = a.x;
                KsT[(d + 1) * KT_STRIDE + row] = a.y;
                KsT[(d + 2) * KT_STRIDE + row] = a.z;
                KsT[(d + 3) * KT_STRIDE + row] = a.w;
                float4 b = kp4[row * 16 + c4];
                KsT[(64 + d + 0) * KT_STRIDE + row] = b.x;
                KsT[(64 + d + 1) * KT_STRIDE + row] = b.y;
                KsT[(64 + d + 2) * KT_STRIDE + row] = b.z;
                KsT[(64 + d + 3) * KT_STRIDE + row] = b.w;
            }
            const float4* v4 = (const float4*)(Vg + base + (long)kt * BK * DIM);
            for (int i = tid; i < BK * 16; i += NTHREAD) {
                ((float4*)Vs)[i] = v4[i];
            }
        }
        __syncthreads();

        // ---- Scores: s[r][c], c0 = lane, c1 = lane+32 ----
        float s0[8], s1[8];
        #pragma unroll
        for (int r = 0; r < 8; r++) { s0[r] = 0.f; s1[r] = 0.f; }

        for (int kk = 0; kk < DQK; kk += 4) {
            float4 q4r[8];
            #pragma unroll
            for (int r = 0; r < 8; r++)
                q4r[r] = *(const float4*)&Qs[(qr0 + r) * DQK + kk];

            float ka0 = KsT[(kk + 0) * KT_STRIDE + lane];
            float kb0 = KsT[(kk + 0) * KT_STRIDE + lane + 32];
            float ka1 = KsT[(kk + 1) * KT_STRIDE + lane];
            float kb1 = KsT[(kk + 1) * KT_STRIDE + lane + 32];
            float ka2 = KsT[(kk + 2) * KT_STRIDE + lane];
            float kb2 = KsT[(kk + 2) * KT_STRIDE + lane + 32];
            float ka3 = KsT[(kk + 3) * KT_STRIDE + lane];
            float kb3 = KsT[(kk + 3) * KT_STRIDE + lane + 32];

            #pragma unroll
            for (int r = 0; r < 8; r++) {
                s0[r] += q4r[r].x * ka0; s1[r] += q4r[r].x * kb0;
                s0[r] += q4r[r].y * ka1; s1[r] += q4r[r].y * kb1;
                s0[r] += q4r[r].z * ka2; s1[r] += q4r[r].z * kb2;
                s0[r] += q4r[r].w * ka3; s1[r] += q4r[r].w * kb3;
            }
        }

        // ---- Online softmax per q row (warp-wide reduction) ----
        #pragma unroll
        for (int r = 0; r < 8; r++) {
            float a = s0[r] * scale;
            float b = s1[r] * scale;
            float v = fmaxf(a, b);
            #pragma unroll
            for (int off = 16; off > 0; off >>= 1)
                v = fmaxf(v, __shfl_xor_sync(0xFFFFFFFFu, v, off));
            float mn = fmaxf(mrow[r], v);
            float f  = __expf(mrow[r] - mn);
            float p0 = __expf(a - mn);
            float p1 = __expf(b - mn);
            float ps = p0 + p1;
            #pragma unroll
            for (int off = 16; off > 0; off >>= 1)
                ps += __shfl_xor_sync(0xFFFFFFFFu, ps, off);
            lrow[r] = lrow[r] * f + ps;
            mrow[r] = mn;
            acc0[r] *= f;
            acc1[r] *= f;
            PsW[r * BK + lane]      = p0;
            PsW[r * BK + lane + 32] = p1;
        }
        __syncwarp();

        // ---- PV: acc[r][d] += sum_k P[r][k] * V[k][d]  (d = lane, lane+32) ----
        for (int k0 = 0; k0 < BK; k0 += 4) {
            float4 p4[8];
            #pragma unroll
            for (int r = 0; r < 8; r++)
                p4[r] = *(const float4*)&PsW[r * BK + k0];

            float va0 = Vs[(k0 + 0) * DV + lane];
            float vb0 = Vs[(k0 + 0) * DV + lane + 32];
            float va1 = Vs[(k0 + 1) * DV + lane];
            float vb1 = Vs[(k0 + 1) * DV + lane + 32];
            float va2 = Vs[(k0 + 2) * DV + lane];
            float vb2 = Vs[(k0 + 2) * DV + lane + 32];
            float va3 = Vs[(k0 + 3) * DV + lane];
            float vb3 = Vs[(k0 + 3) * DV + lane + 32];

            #pragma unroll
            for (int r = 0; r < 8; r++) {
                acc0[r] += p4[r].x * va0; acc1[r] += p4[r].x * vb0;
                acc0[r] += p4[r].y * va1; acc1[r] += p4[r].y * vb1;
                acc0[r] += p4[r].z * va2; acc1[r] += p4[r].z * vb2;
                acc0[r] += p4[r].w * va3; acc1[r] += p4[r].w * vb3;
            }
        }
        __syncwarp();  // Ps reads done before next iteration's writes
    }

    // ---- Epilogue: normalize and write ----
    #pragma unroll
    for (int r = 0; r < 8; r++) {
        float inv = 1.0f / lrow[r];
        long qrow = (long)qtile * BQ + qr0 + r;
        float* o = Og + base + qrow * DIM;
        o[lane]      = acc0[r] * inv;
        o[lane + 32] = acc1[r] * inv;
    }
}

extern "C" void kernel_launch(void* const* d_in, const int* in_sizes, int n_in,
                              void* d_out, int out_size)
{
    const float* Q  = (const float*)d_in[0];
    const float* K  = (const float*)d_in[1];
    const float* V  = (const float*)d_in[2];
    const float* Qp = (const float*)d_in[3];
    const float* Kp = (const float*)d_in[4];
    float* O = (float*)d_out;

    cudaFuncSetAttribute(flash_attn_kernel,
                         cudaFuncAttributeMaxDynamicSharedMemorySize, SMEM_BYTES);

    dim3 grid(SEQ / BQ, BATCH * HEADS);
    flash_attn_kernel<<<grid, NTHREAD, SMEM_BYTES>>>(Q, K, V, Qp, Kp, O);
}

// round 2
// speedup vs baseline: 5.0850x; 5.0850x over previous
#include <cuda_runtime.h>
#include <cuda_bf16.h>

#define BATCH 2
#define HEADS 16
#define SEQ   2048
#define D     64
#define DQK   128      // concat [Q|Qp] feature dim

#define BQ    128      // q rows per CTA
#define BK    64       // kv rows per tile
#define NW    8
#define NT    256

// smem: Khi[64x128 bf16, 256B rows, swizzled] + Klo + VThi[64x64 bf16, 128B rows] + VTlo
#define KH_OFF 0
#define KL_OFF 16384
#define VH_OFF 32768
#define VL_OFF 40960
#define SMEM_BYTES 49152

// split fp32 pair -> packed bf16x2 hi and lo (x in low half, y in high half)
__device__ __forceinline__ void split2(float x, float y, unsigned &hi, unsigned &lo) {
    __nv_bfloat162 h = __floats2bfloat162_rn(x, y);
    hi = *reinterpret_cast<unsigned*>(&h);
    float rx = x - __bfloat162float(h.x);
    float ry = y - __bfloat162float(h.y);
    __nv_bfloat162 l2 = __floats2bfloat162_rn(rx, ry);
    lo = *reinterpret_cast<unsigned*>(&l2);
}

#define MMA(c, a, b0, b1)                                                      \
    asm volatile(                                                              \
        "mma.sync.aligned.m16n8k16.row.col.f32.bf16.bf16.f32 "                 \
        "{%0,%1,%2,%3},{%4,%5,%6,%7},{%8,%9},{%0,%1,%2,%3};"                   \
        : "+f"(c[0]), "+f"(c[1]), "+f"(c[2]), "+f"(c[3])                       \
        : "r"(a[0]), "r"(a[1]), "r"(a[2]), "r"(a[3]), "r"(b0), "r"(b1))

__global__ __launch_bounds__(NT, 1)
void fa2_mma_kernel(const float* __restrict__ Qg,
                    const float* __restrict__ Kg,
                    const float* __restrict__ Vg,
                    const float* __restrict__ Qpg,
                    const float* __restrict__ Kpg,
                    float* __restrict__ Og)
{
    extern __shared__ unsigned char sm[];
    unsigned char* KH = sm + KH_OFF;
    unsigned char* KL = sm + KL_OFF;
    unsigned char* VH = sm + VH_OFF;
    unsigned char* VL = sm + VL_OFF;

    const int bh    = blockIdx.y;
    const int qtile = blockIdx.x;
    const int tid   = threadIdx.x;
    const int w     = tid >> 5;
    const int lane  = tid & 31;
    const int g     = lane >> 2;     // group (row within fragment)
    const int t     = lane & 3;      // thread-in-group (col pairs)

    const long plane = (long)bh * SEQ * D;
    const float* Qpl  = Qg  + plane;
    const float* Kpl  = Kg  + plane;
    const float* Vpl  = Vg  + plane;
    const float* Qppl = Qpg + plane;
    const float* Kppl = Kpg + plane;

    // ---- Q fragments in registers for the whole kernel (scale 1/8 folded in) ----
    // chunk c covers k = 16c..16c+15 of DQK; c<4 -> Q, c>=4 -> Qp
    unsigned qhi[8][4], qlo[8][4];
    {
        const int r0 = qtile * BQ + w * 16 + g;
        #pragma unroll
        for (int c = 0; c < 8; c++) {
            const float* S = (c < 4) ? Qpl : Qppl;
            const int cb = (c & 3) * 16;
            float2 x0 = *(const float2*)&S[(long)r0 * D + cb + 2 * t];
            float2 x1 = *(const float2*)&S[(long)(r0 + 8) * D + cb + 2 * t];
            float2 x2 = *(const float2*)&S[(long)r0 * D + cb + 8 + 2 * t];
            float2 x3 = *(const float2*)&S[(long)(r0 + 8) * D + cb + 8 + 2 * t];
            split2(x0.x * 0.125f, x0.y * 0.125f, qhi[c][0], qlo[c][0]);
            split2(x1.x * 0.125f, x1.y * 0.125f, qhi[c][1], qlo[c][1]);
            split2(x2.x * 0.125f, x2.y * 0.125f, qhi[c][2], qlo[c][2]);
            split2(x3.x * 0.125f, x3.y * 0.125f, qhi[c][3], qlo[c][3]);
        }
    }

    float ov[8][4];
    #pragma unroll
    for (int j = 0; j < 8; j++) { ov[j][0]=0.f; ov[j][1]=0.f; ov[j][2]=0.f; ov[j][3]=0.f; }
    float m0 = -1e30f, m1 = -1e30f, l0 = 0.f, l1 = 0.f;

    for (int kt = 0; kt < SEQ / BK; kt++) {
        __syncthreads();

        // ---- stage K|Kp tile as split bf16, rows=kv (256B), chunk-swizzled ----
        {
            const float* Kt  = Kpl  + (long)kt * BK * D;
            const float* Kpt = Kppl + (long)kt * BK * D;
            #pragma unroll
            for (int i = tid; i < BK * 64; i += NT) {           // (row, col b32-pair)
                int row = i >> 6, col = i & 63;
                const float* src = (col < 32) ? Kt : Kpt;
                float2 v = *(const float2*)&src[row * D + (col & 31) * 2];
                unsigned hi, lo; split2(v.x, v.y, hi, lo);
                unsigned off = row * 256 + (((col >> 2) ^ (row & 7)) << 4) + ((col & 3) << 2);
                *(unsigned*)(KH + off) = hi;
                *(unsigned*)(KL + off) = lo;
            }
            // ---- stage V transposed: rows=d (128B), cols=kv, split bf16 ----
            const float* Vt = Vpl + (long)kt * BK * D;
            #pragma unroll
            for (int i = tid; i < D * 32; i += NT) {            // (d, kv-pair)
                int d = i & 63, cp = i >> 6;
                float x = Vt[(2 * cp) * D + d];
                float y = Vt[(2 * cp + 1) * D + d];
                unsigned hi, lo; split2(x, y, hi, lo);
                unsigned off = d * 128 + (((cp >> 2) ^ (d & 7)) << 4) + ((cp & 3) << 2);
                *(unsigned*)(VH + off) = hi;
                *(unsigned*)(VL + off) = lo;
            }
        }
        __syncthreads();

        // ---- QK^T: sc[j] = 16x8 scores for kv cols 8j..8j+7 ----
        float sc[8][4];
        #pragma unroll
        for (int j = 0; j < 8; j++) { sc[j][0]=0.f; sc[j][1]=0.f; sc[j][2]=0.f; sc[j][3]=0.f; }

        #pragma unroll
        for (int c = 0; c < 8; c++) {
            #pragma unroll
            for (int j = 0; j < 8; j++) {
                const int row = 8 * j + g;                       // row&7 == g
                const unsigned base = row * 256 + (t << 2);
                unsigned o0 = base + (((2 * c)     ^ g) << 4);
                unsigned o1 = base + (((2 * c + 1) ^ g) << 4);
                unsigned bh0 = *(const unsigned*)(KH + o0);
                unsigned bh1 = *(const unsigned*)(KH + o1);
                unsigned bl0 = *(const unsigned*)(KL + o0);
                unsigned bl1 = *(const unsigned*)(KL + o1);
                MMA(sc[j], qhi[c], bh0, bh1);
                MMA(sc[j], qhi[c], bl0, bl1);
                MMA(sc[j], qlo[c], bh0, bh1);
            }
        }

        // ---- online softmax (rows g and g+8; stats shared across quad) ----
        float mx0 = -1e30f, mx1 = -1e30f;
        #pragma unroll
        for (int j = 0; j < 8; j++) {
            mx0 = fmaxf(mx0, fmaxf(sc[j][0], sc[j][1]));
            mx1 = fmaxf(mx1, fmaxf(sc[j][2], sc[j][3]));
        }
        mx0 = fmaxf(mx0, __shfl_xor_sync(0xffffffffu, mx0, 1));
        mx0 = fmaxf(mx0, __shfl_xor_sync(0xffffffffu, mx0, 2));
        mx1 = fmaxf(mx1, __shfl_xor_sync(0xffffffffu, mx1, 1));
        mx1 = fmaxf(mx1, __shfl_xor_sync(0xffffffffu, mx1, 2));

        float mn0 = fmaxf(m0, mx0), mn1 = fmaxf(m1, mx1);
        float f0 = __expf(m0 - mn0), f1 = __expf(m1 - mn1);
        m0 = mn0; m1 = mn1;

        float s0 = 0.f, s1 = 0.f;
        #pragma unroll
        for (int j = 0; j < 8; j++) {
            sc[j][0] = __expf(sc[j][0] - m0); s0 += sc[j][0];
            sc[j][1] = __expf(sc[j][1] - m0); s0 += sc[j][1];
            sc[j][2] = __expf(sc[j][2] - m1); s1 += sc[j][2];
            sc[j][3] = __expf(sc[j][3] - m1); s1 += sc[j][3];
        }
        s0 += __shfl_xor_sync(0xffffffffu, s0, 1);
        s0 += __shfl_xor_sync(0xffffffffu, s0, 2);
        s1 += __shfl_xor_sync(0xffffffffu, s1, 1);
        s1 += __shfl_xor_sync(0xffffffffu, s1, 2);
        l0 = l0 * f0 + s0;
        l1 = l1 * f1 + s1;

        #pragma unroll
        for (int j = 0; j < 8; j++) {
            ov[j][0] *= f0; ov[j][1] *= f0; ov[j][2] *= f1; ov[j][3] *= f1;
        }

        // ---- PV: A = P (register reuse, split bf16), B = V^T tiles ----
        #pragma unroll
        for (int c2 = 0; c2 < 4; c2++) {                        // kv chunk of 16
            unsigned pah[4], pal[4];
            split2(sc[2*c2][0],   sc[2*c2][1],   pah[0], pal[0]);
            split2(sc[2*c2][2],   sc[2*c2][3],   pah[1], pal[1]);
            split2(sc[2*c2+1][0], sc[2*c2+1][1], pah[2], pal[2]);
            split2(sc[2*c2+1][2], sc[2*c2+1][3], pah[3], pal[3]);
            #pragma unroll
            for (int jd = 0; jd < 8; jd++) {                    // d cols 8jd..8jd+7
                const int row = 8 * jd + g;
                const unsigned base = row * 128 + (t << 2);
                unsigned o0 = base + (((2 * c2)     ^ g) << 4);
                unsigned o1 = base + (((2 * c2 + 1) ^ g) << 4);
                unsigned vh0 = *(const unsigned*)(VH + o0);
                unsigned vh1 = *(const unsigned*)(VH + o1);
                unsigned vl0 = *(const unsigned*)(VL + o0);
                unsigned vl1 = *(const unsigned*)(VL + o1);
                MMA(ov[jd], pah, vh0, vh1);
                MMA(ov[jd], pah, vl0, vl1);
                MMA(ov[jd], pal, vh0, vh1);
            }
        }
    }

    // ---- epilogue ----
    {
        float inv0 = 1.0f / l0, inv1 = 1.0f / l1;
        const int r0 = qtile * BQ + w * 16 + g;
        float* O = Og + plane;
        #pragma unroll
        for (int jd = 0; jd < 8; jd++) {
            int col = 8 * jd + 2 * t;
            float2 a = make_float2(ov[jd][0] * inv0, ov[jd][1] * inv0);
            float2 b = make_float2(ov[jd][2] * inv1, ov[jd][3] * inv1);
            *(float2*)&O[(long)r0 * D + col]       = a;
            *(float2*)&O[(long)(r0 + 8) * D + col] = b;
        }
    }
}

extern "C" void kernel_launch(void* const* d_in, const int* in_sizes, int n_in,
                              void* d_out, int out_size)
{
    const float* Q  = (const float*)d_in[0];
    const float* K  = (const float*)d_in[1];
    const float* V  = (const float*)d_in[2];
    const float* Qp = (const float*)d_in[3];
    const float* Kp = (const float*)d_in[4];
    float* O = (float*)d_out;

    cudaFuncSetAttribute(fa2_mma_kernel,
                         cudaFuncAttributeMaxDynamicSharedMemorySize, SMEM_BYTES);

    dim3 grid(SEQ / BQ, BATCH * HEADS);
    fa2_mma_kernel<<<grid, NT, SMEM_BYTES>>>(Q, K, V, Qp, Kp, O);
}

// round 4
// speedup vs baseline: 6.5533x; 1.2887x over previous
#include <cuda_runtime.h>
#include <cuda_bf16.h>
#include <cstdint>

#define BATCH 2
#define HEADS 16
#define BH    32
#define SEQ   2048
#define D     64
#define DQK   128

#define BQ    128
#define BK    64
#define NTILE (SEQ / BK)      // 32
#define NT    256

// per-tile packed image sizes (bytes)
#define KTILE_B 16384         // 64 rows x 256B (128 bf16)
#define VTILE_B 8192          // 64 d-rows x 128B (64 bf16)

// smem: two stages of [KH | KL | VH | VL] + 2 mbarriers
#define STAGE_B  (KTILE_B + KTILE_B + VTILE_B + VTILE_B)   // 49152
#define SM_KH    0
#define SM_KL    16384
#define SM_VH    32768
#define SM_VL    40960
#define SM_MBAR  (2 * STAGE_B)                             // 98304
#define SMEM_BYTES (SM_MBAR + 16)

#define QSCALE 0.18033688011112042f   // 0.125 * log2(e)

// ---- 48MB device scratch: packed split-bf16 tile images ----
__device__ __align__(128) unsigned char gKH[BH * NTILE * KTILE_B];
__device__ __align__(128) unsigned char gKL[BH * NTILE * KTILE_B];
__device__ __align__(128) unsigned char gVH[BH * NTILE * VTILE_B];
__device__ __align__(128) unsigned char gVL[BH * NTILE * VTILE_B];

__device__ __forceinline__ void split2(float x, float y, unsigned &hi, unsigned &lo) {
    __nv_bfloat162 h = __floats2bfloat162_rn(x, y);
    hi = *reinterpret_cast<unsigned*>(&h);
    float rx = x - __bfloat162float(h.x);
    float ry = y - __bfloat162float(h.y);
    __nv_bfloat162 l2 = __floats2bfloat162_rn(rx, ry);
    lo = *reinterpret_cast<unsigned*>(&l2);
}

#define MMA(c, a, b0, b1)                                                      \
    asm volatile(                                                              \
        "mma.sync.aligned.m16n8k16.row.col.f32.bf16.bf16.f32 "                 \
        "{%0,%1,%2,%3},{%4,%5,%6,%7},{%8,%9},{%0,%1,%2,%3};"                   \
        : "+f"(c[0]), "+f"(c[1]), "+f"(c[2]), "+f"(c[3])                       \
        : "r"(a[0]), "r"(a[1]), "r"(a[2]), "r"(a[3]), "r"(b0), "r"(b1))

// ======================= pre-pass: pack K|Kp and V^T =======================
__global__ __launch_bounds__(NT)
void pack_kv(const float* __restrict__ K, const float* __restrict__ Kp,
             const float* __restrict__ V)
{
    const int kt = blockIdx.x, bh = blockIdx.y, tid = threadIdx.x;
    const long plane = (long)bh * SEQ * D;
    const float* Kt  = K  + plane + (long)kt * BK * D;
    const float* Kpt = Kp + plane + (long)kt * BK * D;
    const float* Vt  = V  + plane + (long)kt * BK * D;
    const size_t ti = (size_t)(bh * NTILE + kt);
    unsigned char* tKH = gKH + ti * KTILE_B;
    unsigned char* tKL = gKL + ti * KTILE_B;
    unsigned char* tVH = gVH + ti * VTILE_B;
    unsigned char* tVL = gVL + ti * VTILE_B;

    // K|Kp: rows=kv, 64 b32-pair cols (swizzled 16B chunks)
    for (int i = tid; i < BK * 64; i += NT) {
        int row = i >> 6, col = i & 63;
        const float* src = (col < 32) ? Kt : Kpt;
        float2 v = *(const float2*)&src[row * D + (col & 31) * 2];
        unsigned hi, lo; split2(v.x, v.y, hi, lo);
        unsigned off = row * 256 + (((col >> 2) ^ (row & 7)) << 4) + ((col & 3) << 2);
        *(unsigned*)(tKH + off) = hi;
        *(unsigned*)(tKL + off) = lo;
    }
    // V transposed: rows=d, cols=kv pairs
    for (int i = tid; i < D * 32; i += NT) {
        int d = i & 63, cp = i >> 6;
        float x = Vt[(2 * cp) * D + d];
        float y = Vt[(2 * cp + 1) * D + d];
        unsigned hi, lo; split2(x, y, hi, lo);
        unsigned off = d * 128 + (((cp >> 2) ^ (d & 7)) << 4) + ((cp & 3) << 2);
        *(unsigned*)(tVH + off) = hi;
        *(unsigned*)(tVL + off) = lo;
    }
}

// =============================== main kernel ===============================
__device__ __forceinline__ uint32_t s2u32(const void* p) {
    uint32_t a;
    asm("{ .reg .u64 t; cvta.to.shared.u64 t, %1; cvt.u32.u64 %0, t; }" : "=r"(a) : "l"(p));
    return a;
}

__device__ __forceinline__ void bulk_g2s(uint32_t dst, const void* src,
                                         unsigned bytes, uint32_t mbar) {
    asm volatile(
        "cp.async.bulk.shared::cluster.global.mbarrier::complete_tx::bytes "
        "[%0], [%1], %2, [%3];"
        :: "r"(dst), "l"(src), "r"(bytes), "r"(mbar) : "memory");
}

__global__ __launch_bounds__(NT, 1)
void fa3_mma_kernel(const float* __restrict__ Qg,
                    const float* __restrict__ Qpg,
                    float* __restrict__ Og)
{
    extern __shared__ unsigned char sm[];
    const uint32_t smb = s2u32(sm);

    const int bh    = blockIdx.y;
    const int qtile = blockIdx.x;
    const int tid   = threadIdx.x;
    const int w     = tid >> 5;
    const int lane  = tid & 31;
    const int g     = lane >> 2;
    const int t     = lane & 3;

    const long plane = (long)bh * SEQ * D;

    if (tid == 0) {
        asm volatile("mbarrier.init.shared.b64 [%0], 1;" :: "r"(smb + SM_MBAR) : "memory");
        asm volatile("mbarrier.init.shared.b64 [%0], 1;" :: "r"(smb + SM_MBAR + 8) : "memory");
    }
    __syncthreads();

    // ---- Q fragments in registers (scale = 0.125*log2e folded in) ----
    unsigned qhi[8][4], qlo[8][4];
    {
        const float* Qpl  = Qg  + plane;
        const float* Qppl = Qpg + plane;
        const int r0 = qtile * BQ + w * 16 + g;
        #pragma unroll
        for (int c = 0; c < 8; c++) {
            const float* S = (c < 4) ? Qpl : Qppl;
            const int cb = (c & 3) * 16;
            float2 x0 = *(const float2*)&S[(long)r0 * D + cb + 2 * t];
            float2 x1 = *(const float2*)&S[(long)(r0 + 8) * D + cb + 2 * t];
            float2 x2 = *(const float2*)&S[(long)r0 * D + cb + 8 + 2 * t];
            float2 x3 = *(const float2*)&S[(long)(r0 + 8) * D + cb + 8 + 2 * t];
            split2(x0.x * QSCALE, x0.y * QSCALE, qhi[c][0], qlo[c][0]);
            split2(x1.x * QSCALE, x1.y * QSCALE, qhi[c][1], qlo[c][1]);
            split2(x2.x * QSCALE, x2.y * QSCALE, qhi[c][2], qlo[c][2]);
            split2(x3.x * QSCALE, x3.y * QSCALE, qhi[c][3], qlo[c][3]);
        }
    }

    float ov[8][4];
    #pragma unroll
    for (int j = 0; j < 8; j++) { ov[j][0]=0.f; ov[j][1]=0.f; ov[j][2]=0.f; ov[j][3]=0.f; }
    float m0 = -1e30f, m1 = -1e30f, l0 = 0.f, l1 = 0.f;

    // issue tile kt into stage s (thread 0)
    auto issue = [&](int kt, int s) {
        if (tid == 0) {
            const uint32_t mb = smb + SM_MBAR + s * 8;
            asm volatile("mbarrier.arrive.expect_tx.shared.b64 _, [%0], %1;"
                         :: "r"(mb), "r"((unsigned)STAGE_B) : "memory");
            const size_t ti = (size_t)(bh * NTILE + kt);
            const uint32_t sb = smb + s * STAGE_B;
            bulk_g2s(sb + SM_KH, gKH + ti * KTILE_B, KTILE_B, mb);
            bulk_g2s(sb + SM_KL, gKL + ti * KTILE_B, KTILE_B, mb);
            bulk_g2s(sb + SM_VH, gVH + ti * VTILE_B, VTILE_B, mb);
            bulk_g2s(sb + SM_VL, gVL + ti * VTILE_B, VTILE_B, mb);
        }
    };

    issue(0, 0);

    for (int kt = 0; kt < NTILE; kt++) {
        const int s = kt & 1;
        if (kt + 1 < NTILE) issue(kt + 1, s ^ 1);

        // wait full(stage s), phase = (kt>>1)&1
        {
            const uint32_t mb = smb + SM_MBAR + s * 8;
            const unsigned ph = (kt >> 1) & 1;
            unsigned done = 0;
            while (!done) {
                asm volatile(
                    "{ .reg .pred p; "
                    "mbarrier.try_wait.parity.acquire.cta.shared::cta.b64 p, [%1], %2; "
                    "selp.b32 %0, 1, 0, p; }"
                    : "=r"(done) : "r"(mb), "r"(ph) : "memory");
            }
        }

        unsigned char* KH = sm + s * STAGE_B + SM_KH;
        unsigned char* KL = sm + s * STAGE_B + SM_KL;
        unsigned char* VH = sm + s * STAGE_B + SM_VH;
        unsigned char* VL = sm + s * STAGE_B + SM_VL;

        // ---- QK^T ----
        float sc[8][4];
        #pragma unroll
        for (int j = 0; j < 8; j++) { sc[j][0]=0.f; sc[j][1]=0.f; sc[j][2]=0.f; sc[j][3]=0.f; }

        #pragma unroll
        for (int c = 0; c < 8; c++) {
            #pragma unroll
            for (int jp = 0; jp < 4; jp++) {
                const int j0 = 2 * jp, j1 = 2 * jp + 1;
                const unsigned base0 = (8 * j0 + g) * 256 + (t << 2);
                const unsigned base1 = (8 * j1 + g) * 256 + (t << 2);
                const unsigned ch0 = ((2 * c) ^ g) << 4, ch1 = ((2 * c + 1) ^ g) << 4;
                unsigned ah0 = *(const unsigned*)(KH + base0 + ch0);
                unsigned ah1 = *(const unsigned*)(KH + base0 + ch1);
                unsigned bh0 = *(const unsigned*)(KH + base1 + ch0);
                unsigned bh1 = *(const unsigned*)(KH + base1 + ch1);
                unsigned al0 = *(const unsigned*)(KL + base0 + ch0);
                unsigned al1 = *(const unsigned*)(KL + base0 + ch1);
                unsigned bl0 = *(const unsigned*)(KL + base1 + ch0);
                unsigned bl1 = *(const unsigned*)(KL + base1 + ch1);
                MMA(sc[j0], qhi[c], ah0, ah1);
                MMA(sc[j1], qhi[c], bh0, bh1);
                MMA(sc[j0], qhi[c], al0, al1);
                MMA(sc[j1], qhi[c], bl0, bl1);
                MMA(sc[j0], qlo[c], ah0, ah1);
                MMA(sc[j1], qlo[c], bh0, bh1);
            }
        }

        // ---- online softmax (log2 domain) ----
        float mx0 = -1e30f, mx1 = -1e30f;
        #pragma unroll
        for (int j = 0; j < 8; j++) {
            mx0 = fmaxf(mx0, fmaxf(sc[j][0], sc[j][1]));
            mx1 = fmaxf(mx1, fmaxf(sc[j][2], sc[j][3]));
        }
        mx0 = fmaxf(mx0, __shfl_xor_sync(0xffffffffu, mx0, 1));
        mx0 = fmaxf(mx0, __shfl_xor_sync(0xffffffffu, mx0, 2));
        mx1 = fmaxf(mx1, __shfl_xor_sync(0xffffffffu, mx1, 1));
        mx1 = fmaxf(mx1, __shfl_xor_sync(0xffffffffu, mx1, 2));

        float mn0 = fmaxf(m0, mx0), mn1 = fmaxf(m1, mx1);
        float f0 = exp2f(m0 - mn0), f1 = exp2f(m1 - mn1);
        m0 = mn0; m1 = mn1;

        float s0 = 0.f, s1 = 0.f;
        #pragma unroll
        for (int j = 0; j < 8; j++) {
            sc[j][0] = exp2f(sc[j][0] - m0); s0 += sc[j][0];
            sc[j][1] = exp2f(sc[j][1] - m0); s0 += sc[j][1];
            sc[j][2] = exp2f(sc[j][2] - m1); s1 += sc[j][2];
            sc[j][3] = exp2f(sc[j][3] - m1); s1 += sc[j][3];
        }
        s0 += __shfl_xor_sync(0xffffffffu, s0, 1);
        s0 += __shfl_xor_sync(0xffffffffu, s0, 2);
        s1 += __shfl_xor_sync(0xffffffffu, s1, 1);
        s1 += __shfl_xor_sync(0xffffffffu, s1, 2);
        l0 = l0 * f0 + s0;
        l1 = l1 * f1 + s1;

        #pragma unroll
        for (int j = 0; j < 8; j++) {
            ov[j][0] *= f0; ov[j][1] *= f0; ov[j][2] *= f1; ov[j][3] *= f1;
        }

        // ---- PV ----
        #pragma unroll
        for (int c2 = 0; c2 < 4; c2++) {
            unsigned pah[4], pal[4];
            split2(sc[2*c2][0],   sc[2*c2][1],   pah[0], pal[0]);
            split2(sc[2*c2][2],   sc[2*c2][3],   pah[1], pal[1]);
            split2(sc[2*c2+1][0], sc[2*c2+1][1], pah[2], pal[2]);
            split2(sc[2*c2+1][2], sc[2*c2+1][3], pah[3], pal[3]);
            #pragma unroll
            for (int jp = 0; jp < 4; jp++) {
                const int j0 = 2 * jp, j1 = 2 * jp + 1;
                const unsigned base0 = (8 * j0 + g) * 128 + (t << 2);
                const unsigned base1 = (8 * j1 + g) * 128 + (t << 2);
                const unsigned ch0 = ((2 * c2) ^ g) << 4, ch1 = ((2 * c2 + 1) ^ g) << 4;
                unsigned vh00 = *(const unsigned*)(VH + base0 + ch0);
                unsigned vh01 = *(const unsigned*)(VH + base0 + ch1);
                unsigned vh10 = *(const unsigned*)(VH + base1 + ch0);
                unsigned vh11 = *(const unsigned*)(VH + base1 + ch1);
                unsigned vl00 = *(const unsigned*)(VL + base0 + ch0);
                unsigned vl01 = *(const unsigned*)(VL + base0 + ch1);
                unsigned vl10 = *(const unsigned*)(VL + base1 + ch0);
                unsigned vl11 = *(const unsigned*)(VL + base1 + ch1);
                MMA(ov[j0], pah, vh00, vh01);
                MMA(ov[j1], pah, vh10, vh11);
                MMA(ov[j0], pah, vl00, vl01);
                MMA(ov[j1], pah, vl10, vl11);
                MMA(ov[j0], pal, vh00, vh01);
                MMA(ov[j1], pal, vh10, vh11);
            }
        }

        __syncthreads();   // stage s fully consumed by all warps before reuse
    }

    // ---- epilogue ----
    {
        float inv0 = 1.0f / l0, inv1 = 1.0f / l1;
        const int r0 = qtile * BQ + w * 16 + g;
        float* O = Og + plane;
        #pragma unroll
        for (int jd = 0; jd < 8; jd++) {
            int col = 8 * jd + 2 * t;
            float2 a = make_float2(ov[jd][0] * inv0, ov[jd][1] * inv0);
            float2 b = make_float2(ov[jd][2] * inv1, ov[jd][3] * inv1);
            *(float2*)&O[(long)r0 * D + col]       = a;
            *(float2*)&O[(long)(r0 + 8) * D + col] = b;
        }
    }
}

extern "C" void kernel_launch(void* const* d_in, const int* in_sizes, int n_in,
                              void* d_out, int out_size)
{
    const float* Q  = (const float*)d_in[0];
    const float* K  = (const float*)d_in[1];
    const float* V  = (const float*)d_in[2];
    const float* Qp = (const float*)d_in[3];
    const float* Kp = (const float*)d_in[4];
    float* O = (float*)d_out;

    static int configured = 0;
    cudaFuncSetAttribute(fa3_mma_kernel,
                         cudaFuncAttributeMaxDynamicSharedMemorySize, SMEM_BYTES);
    (void)configured;

    dim3 pgrid(NTILE, BH);
    pack_kv<<<pgrid, NT>>>(K, Kp, V);

    dim3 grid(SEQ / BQ, BH);
    fa3_mma_kernel<<<grid, NT, SMEM_BYTES>>>(Q, Qp, O);
}